// round 14
// baseline (speedup 1.0000x reference)
#include <cuda_runtime.h>
#include <cuda_fp16.h>
#include <cstdint>

#define N_NODES 50000
#define D       128
#define CAP     64          // max degree capacity (mean 16, sigma 4 -> safe)
#define GEMM_ROWS 64        // rows per GEMM block (8 warps x 4 row-pairs)
#define GB ((N_NODES + GEMM_ROWS - 1) / GEMM_ROWS)   // 782 gemm blocks

// ---- scratch (static device globals; zero-initialized at load) ----
__device__ uint2 g_Ph[(size_t)N_NODES * 32];        // P in f16: row = 32 uint2
__device__ int   g_cursor[N_NODES];                 // degree counts; re-zeroed by gather
__device__ unsigned int g_slots[(size_t)N_NODES * CAP];  // src | f16(w)<<16

// ---- f32x2 packed-FMA helpers (sm_103a) ----
__device__ __forceinline__ void fma2(unsigned long long& d,
                                     unsigned long long a,
                                     unsigned long long b) {
    asm("fma.rn.f32x2 %0, %1, %2, %0;" : "+l"(d) : "l"(a), "l"(b));
}
__device__ __forceinline__ unsigned long long packdup(float x) {
    unsigned long long r;
    asm("mov.b64 %0, {%1, %1};" : "=l"(r) : "f"(x));
    return r;
}
__device__ __forceinline__ unsigned long long pack2(float a, float b) {
    unsigned long long r;
    asm("mov.b64 %0, {%1, %2};" : "=l"(r) : "f"(a), "f"(b));
    return r;
}
__device__ __forceinline__ float2 unpack2(unsigned long long v) {
    float2 r;
    asm("mov.b64 {%0, %1}, %2;" : "=f"(r.x), "=f"(r.y) : "l"(v));
    return r;
}

// ===========================================================================
// K1: heterogeneous — blocks [0,GB) compute P = feat @ W (f32 math, f16 P
// out); blocks [GB, GB+FB) bucket edges into g_slots (packed int).
// GEMM part identical to R13 (pair-interleaved A, proven).
// ===========================================================================
__global__ void __launch_bounds__(256)
gemm_fill_kernel(const float* __restrict__ feat,
                 const float* __restrict__ W,
                 const int* __restrict__ src,
                 const int* __restrict__ dst,
                 const float* __restrict__ ew,
                 int E) {
    __shared__ unsigned long long sP[GEMM_ROWS / 2][D];   // 32KB pair-interleaved

    if (blockIdx.x >= GB) {
        // ---------------- fill part: one edge per thread ----------------
        int i = (blockIdx.x - GB) * 256 + threadIdx.x;
        if (i < E) {
            int d = __ldg(dst + i);
            int p = atomicAdd(&g_cursor[d], 1);
            if (p < CAP) {
                unsigned short hw =
                    __half_as_ushort(__float2half_rn(__ldg(ew + i)));
                g_slots[(size_t)d * CAP + p] =
                    (unsigned int)__ldg(src + i) | ((unsigned int)hw << 16);
            }
        }
        return;
    }

    // ------------- GEMM part: 64 rows = 32 pairs, 4 pairs per warp -------------
    const int t = threadIdx.x;
    const int block_row = blockIdx.x * GEMM_ROWS;

    #pragma unroll
    for (int it = 0; it < (GEMM_ROWS / 2 * 32) / 256; it++) {
        int i  = it * 256 + t;
        int p  = i >> 5;
        int c4 = i & 31;
        int row0 = block_row + 2 * p;
        float4 f0 = (row0 < N_NODES)
            ? __ldg(reinterpret_cast<const float4*>(feat + (size_t)row0 * D) + c4)
            : make_float4(0.f, 0.f, 0.f, 0.f);
        float4 f1 = (row0 + 1 < N_NODES)
            ? __ldg(reinterpret_cast<const float4*>(feat + (size_t)(row0 + 1) * D) + c4)
            : make_float4(0.f, 0.f, 0.f, 0.f);
        sP[p][c4 * 4 + 0] = pack2(f0.x, f1.x);
        sP[p][c4 * 4 + 1] = pack2(f0.y, f1.y);
        sP[p][c4 * 4 + 2] = pack2(f0.z, f1.z);
        sP[p][c4 * 4 + 3] = pack2(f0.w, f1.w);
    }
    __syncthreads();

    const int warp = t >> 5;
    const int lane = t & 31;
    const int p0 = warp * 4;

    unsigned long long acc[4][4];
    #pragma unroll
    for (int p = 0; p < 4; p++)
        #pragma unroll
        for (int c = 0; c < 4; c++) acc[p][c] = 0ull;

    const float4* W4 = reinterpret_cast<const float4*>(W);

    #pragma unroll 2
    for (int k = 0; k < D; k++) {
        float4 w = __ldg(W4 + k * (D / 4) + lane);
        unsigned long long w0 = packdup(w.x);
        unsigned long long w1 = packdup(w.y);
        unsigned long long w2 = packdup(w.z);
        unsigned long long w3 = packdup(w.w);
        #pragma unroll
        for (int p = 0; p < 4; p++) {
            unsigned long long a = sP[p0 + p][k];
            fma2(acc[p][0], a, w0);
            fma2(acc[p][1], a, w1);
            fma2(acc[p][2], a, w2);
            fma2(acc[p][3], a, w3);
        }
    }

    #pragma unroll
    for (int p = 0; p < 4; p++) {
        float2 c0 = unpack2(acc[p][0]);
        float2 c1 = unpack2(acc[p][1]);
        float2 c2 = unpack2(acc[p][2]);
        float2 c3 = unpack2(acc[p][3]);
        int row0 = block_row + 2 * (p0 + p);
        if (row0 < N_NODES) {
            __half2 h0 = __float22half2_rn(make_float2(c0.x, c1.x));
            __half2 h1 = __float22half2_rn(make_float2(c2.x, c3.x));
            uint2 pk;
            pk.x = *reinterpret_cast<const unsigned int*>(&h0);
            pk.y = *reinterpret_cast<const unsigned int*>(&h1);
            g_Ph[(size_t)row0 * 32 + lane] = pk;
        }
        if (row0 + 1 < N_NODES) {
            __half2 h0 = __float22half2_rn(make_float2(c0.y, c1.y));
            __half2 h1 = __float22half2_rn(make_float2(c2.y, c3.y));
            uint2 pk;
            pk.x = *reinterpret_cast<const unsigned int*>(&h0);
            pk.y = *reinterpret_cast<const unsigned int*>(&h1);
            g_Ph[(size_t)(row0 + 1) * 32 + lane] = pk;
        }
    }
}

// ===========================================================================
// K2: gather.  out[n] = 0.5*(P[n] + sum w*P[src]), P in f16, fp32 accum.
// Slots packed: src in low 16 bits, f16 w in high 16 -> 1 shfl per edge.
// 4-wide unroll + launch_bounds(256,8): <=32 regs, ~full occupancy.
// ===========================================================================
__device__ __forceinline__ float slot_w(unsigned int e) {
    return __half2float(__ushort_as_half((unsigned short)(e >> 16)));
}

__global__ void __launch_bounds__(256, 8)
gather_kernel(float* __restrict__ out) {
    int gid  = blockIdx.x * blockDim.x + threadIdx.x;
    int node = gid >> 5;
    int lane = gid & 31;
    if (node >= N_NODES) return;

    int cnt = g_cursor[node];
    if (cnt > CAP) cnt = CAP;
    const unsigned int* sl = g_slots + (size_t)node * CAP;

    unsigned int my = 0;
    if (lane < cnt) my = __ldg(sl + lane);

    // self term
    float4 acc;
    {
        uint2 pk = g_Ph[(size_t)node * 32 + lane];
        float2 f0 = __half22float2(*reinterpret_cast<const __half2*>(&pk.x));
        float2 f1 = __half22float2(*reinterpret_cast<const __half2*>(&pk.y));
        acc = make_float4(f0.x, f0.y, f1.x, f1.y);
    }

    const int lim = (cnt < 32) ? cnt : 32;
    int i = 0;
    for (; i + 4 <= lim; i += 4) {
        unsigned int e[4];
        #pragma unroll
        for (int j = 0; j < 4; j++)
            e[j] = __shfl_sync(0xFFFFFFFFu, my, i + j);
        uint2 pv[4];
        #pragma unroll
        for (int j = 0; j < 4; j++)
            pv[j] = g_Ph[(size_t)(e[j] & 0xFFFFu) * 32 + lane];
        #pragma unroll
        for (int j = 0; j < 4; j++) {
            float w = slot_w(e[j]);
            float2 f0 = __half22float2(*reinterpret_cast<const __half2*>(&pv[j].x));
            float2 f1 = __half22float2(*reinterpret_cast<const __half2*>(&pv[j].y));
            acc.x += w * f0.x;
            acc.y += w * f0.y;
            acc.z += w * f1.x;
            acc.w += w * f1.y;
        }
    }
    for (; i < lim; i++) {
        unsigned int e = __shfl_sync(0xFFFFFFFFu, my, i);
        float w = slot_w(e);
        uint2 pk = g_Ph[(size_t)(e & 0xFFFFu) * 32 + lane];
        float2 f0 = __half22float2(*reinterpret_cast<const __half2*>(&pk.x));
        float2 f1 = __half22float2(*reinterpret_cast<const __half2*>(&pk.y));
        acc.x += w * f0.x; acc.y += w * f0.y;
        acc.z += w * f1.x; acc.w += w * f1.y;
    }
    for (; i < cnt; i++) {   // rare tail: degree > 32
        unsigned int e = __ldg(sl + i);
        float w = slot_w(e);
        uint2 pk = g_Ph[(size_t)(e & 0xFFFFu) * 32 + lane];
        float2 f0 = __half22float2(*reinterpret_cast<const __half2*>(&pk.x));
        float2 f1 = __half22float2(*reinterpret_cast<const __half2*>(&pk.y));
        acc.x += w * f0.x; acc.y += w * f0.y;
        acc.z += w * f1.x; acc.w += w * f1.y;
    }

    acc.x *= 0.5f; acc.y *= 0.5f; acc.z *= 0.5f; acc.w *= 0.5f;
    reinterpret_cast<float4*>(out)[(size_t)node * 32 + lane] = acc;

    if (lane == 0) g_cursor[node] = 0;   // restore invariant for next call
}

// ===========================================================================
// Launch. Inputs: feature [N*D] f32, edge_src [E] i32, edge_dst [E] i32,
// edge_w [E] f32, weight [D*D] f32. Output: [N*D] f32.
// ===========================================================================
extern "C" void kernel_launch(void* const* d_in, const int* in_sizes, int n_in,
                              void* d_out, int out_size) {
    const float* feat = (const float*)d_in[0];
    const int*   src  = (const int*)d_in[1];
    const int*   dst  = (const int*)d_in[2];
    const float* ew   = (const float*)d_in[3];
    const float* W    = (const float*)d_in[4];
    float* out = (float*)d_out;

    const int E  = in_sizes[1];
    const int FB = (E + 255) / 256;

    gemm_fill_kernel<<<GB + FB, 256>>>(feat, W, src, dst, ew, E);
    gather_kernel<<<(N_NODES * 32 + 255) / 256, 256>>>(out);
}

// round 15
// speedup vs baseline: 1.0217x; 1.0217x over previous
#include <cuda_runtime.h>
#include <cuda_fp16.h>
#include <cstdint>

#define N_NODES 50000
#define D       128
#define CAP     64          // max degree capacity (mean 16, sigma 4 -> safe)
#define GEMM_ROWS 64        // rows per GEMM block (8 warps x 4 row-pairs)
#define GB ((N_NODES + GEMM_ROWS - 1) / GEMM_ROWS)   // 782 gemm blocks

// ---- scratch (static device globals; zero-initialized at load) ----
__device__ uint2 g_Ph[(size_t)N_NODES * 32];        // P in f16: row = 32 uint2
__device__ int   g_cursor[N_NODES];                 // degree counts; re-zeroed by gather
__device__ unsigned int g_slots[(size_t)N_NODES * CAP];  // src | f16(w)<<16

// ---- f32x2 packed-FMA helpers (sm_103a) ----
__device__ __forceinline__ void fma2(unsigned long long& d,
                                     unsigned long long a,
                                     unsigned long long b) {
    asm("fma.rn.f32x2 %0, %1, %2, %0;" : "+l"(d) : "l"(a), "l"(b));
}
__device__ __forceinline__ unsigned long long packdup(float x) {
    unsigned long long r;
    asm("mov.b64 %0, {%1, %1};" : "=l"(r) : "f"(x));
    return r;
}
__device__ __forceinline__ unsigned long long pack2(float a, float b) {
    unsigned long long r;
    asm("mov.b64 %0, {%1, %2};" : "=l"(r) : "f"(a), "f"(b));
    return r;
}
__device__ __forceinline__ float2 unpack2(unsigned long long v) {
    float2 r;
    asm("mov.b64 {%0, %1}, %2;" : "=f"(r.x), "=f"(r.y) : "l"(v));
    return r;
}

// ===========================================================================
// K1: heterogeneous — blocks [0,GB) compute P = feat @ W (f32 math, f16 P
// out); blocks [GB, GB+FB) bucket edges into g_slots (packed int).
// GEMM part identical to R13 (pair-interleaved A, proven).
// ===========================================================================
__global__ void __launch_bounds__(256)
gemm_fill_kernel(const float* __restrict__ feat,
                 const float* __restrict__ W,
                 const int* __restrict__ src,
                 const int* __restrict__ dst,
                 const float* __restrict__ ew,
                 int E) {
    __shared__ unsigned long long sP[GEMM_ROWS / 2][D];   // 32KB pair-interleaved

    if (blockIdx.x >= GB) {
        // ---------------- fill part: one edge per thread ----------------
        int i = (blockIdx.x - GB) * 256 + threadIdx.x;
        if (i < E) {
            int d = __ldg(dst + i);
            int p = atomicAdd(&g_cursor[d], 1);
            if (p < CAP) {
                unsigned short hw =
                    __half_as_ushort(__float2half_rn(__ldg(ew + i)));
                g_slots[(size_t)d * CAP + p] =
                    (unsigned int)__ldg(src + i) | ((unsigned int)hw << 16);
            }
        }
        return;
    }

    // ------------- GEMM part: 64 rows = 32 pairs, 4 pairs per warp -------------
    const int t = threadIdx.x;
    const int block_row = blockIdx.x * GEMM_ROWS;

    #pragma unroll
    for (int it = 0; it < (GEMM_ROWS / 2 * 32) / 256; it++) {
        int i  = it * 256 + t;
        int p  = i >> 5;
        int c4 = i & 31;
        int row0 = block_row + 2 * p;
        float4 f0 = (row0 < N_NODES)
            ? __ldg(reinterpret_cast<const float4*>(feat + (size_t)row0 * D) + c4)
            : make_float4(0.f, 0.f, 0.f, 0.f);
        float4 f1 = (row0 + 1 < N_NODES)
            ? __ldg(reinterpret_cast<const float4*>(feat + (size_t)(row0 + 1) * D) + c4)
            : make_float4(0.f, 0.f, 0.f, 0.f);
        sP[p][c4 * 4 + 0] = pack2(f0.x, f1.x);
        sP[p][c4 * 4 + 1] = pack2(f0.y, f1.y);
        sP[p][c4 * 4 + 2] = pack2(f0.z, f1.z);
        sP[p][c4 * 4 + 3] = pack2(f0.w, f1.w);
    }
    __syncthreads();

    const int warp = t >> 5;
    const int lane = t & 31;
    const int p0 = warp * 4;

    unsigned long long acc[4][4];
    #pragma unroll
    for (int p = 0; p < 4; p++)
        #pragma unroll
        for (int c = 0; c < 4; c++) acc[p][c] = 0ull;

    const float4* W4 = reinterpret_cast<const float4*>(W);

    #pragma unroll 2
    for (int k = 0; k < D; k++) {
        float4 w = __ldg(W4 + k * (D / 4) + lane);
        unsigned long long w0 = packdup(w.x);
        unsigned long long w1 = packdup(w.y);
        unsigned long long w2 = packdup(w.z);
        unsigned long long w3 = packdup(w.w);
        #pragma unroll
        for (int p = 0; p < 4; p++) {
            unsigned long long a = sP[p0 + p][k];
            fma2(acc[p][0], a, w0);
            fma2(acc[p][1], a, w1);
            fma2(acc[p][2], a, w2);
            fma2(acc[p][3], a, w3);
        }
    }

    #pragma unroll
    for (int p = 0; p < 4; p++) {
        float2 c0 = unpack2(acc[p][0]);
        float2 c1 = unpack2(acc[p][1]);
        float2 c2 = unpack2(acc[p][2]);
        float2 c3 = unpack2(acc[p][3]);
        int row0 = block_row + 2 * (p0 + p);
        if (row0 < N_NODES) {
            __half2 h0 = __float22half2_rn(make_float2(c0.x, c1.x));
            __half2 h1 = __float22half2_rn(make_float2(c2.x, c3.x));
            uint2 pk;
            pk.x = *reinterpret_cast<const unsigned int*>(&h0);
            pk.y = *reinterpret_cast<const unsigned int*>(&h1);
            g_Ph[(size_t)row0 * 32 + lane] = pk;
        }
        if (row0 + 1 < N_NODES) {
            __half2 h0 = __float22half2_rn(make_float2(c0.y, c1.y));
            __half2 h1 = __float22half2_rn(make_float2(c2.y, c3.y));
            uint2 pk;
            pk.x = *reinterpret_cast<const unsigned int*>(&h0);
            pk.y = *reinterpret_cast<const unsigned int*>(&h1);
            g_Ph[(size_t)(row0 + 1) * 32 + lane] = pk;
        }
    }
}

// ===========================================================================
// K2: gather.  out[n] = 0.5*(P[n] + sum w*P[src]), P in f16, fp32 accum.
// Slots packed: src in low 16 bits, f16 w in high 16 -> 1 shfl per edge.
// 4-wide unroll + launch_bounds(256,8): <=32 regs, ~full occupancy.
// ===========================================================================
__device__ __forceinline__ float slot_w(unsigned int e) {
    return __half2float(__ushort_as_half((unsigned short)(e >> 16)));
}

__global__ void __launch_bounds__(256, 8)
gather_kernel(float* __restrict__ out) {
    int gid  = blockIdx.x * blockDim.x + threadIdx.x;
    int node = gid >> 5;
    int lane = gid & 31;
    if (node >= N_NODES) return;

    int cnt = g_cursor[node];
    if (cnt > CAP) cnt = CAP;
    const unsigned int* sl = g_slots + (size_t)node * CAP;

    unsigned int my = 0;
    if (lane < cnt) my = __ldg(sl + lane);

    // self term
    float4 acc;
    {
        uint2 pk = g_Ph[(size_t)node * 32 + lane];
        float2 f0 = __half22float2(*reinterpret_cast<const __half2*>(&pk.x));
        float2 f1 = __half22float2(*reinterpret_cast<const __half2*>(&pk.y));
        acc = make_float4(f0.x, f0.y, f1.x, f1.y);
    }

    const int lim = (cnt < 32) ? cnt : 32;
    int i = 0;
    for (; i + 4 <= lim; i += 4) {
        unsigned int e[4];
        #pragma unroll
        for (int j = 0; j < 4; j++)
            e[j] = __shfl_sync(0xFFFFFFFFu, my, i + j);
        uint2 pv[4];
        #pragma unroll
        for (int j = 0; j < 4; j++)
            pv[j] = g_Ph[(size_t)(e[j] & 0xFFFFu) * 32 + lane];
        #pragma unroll
        for (int j = 0; j < 4; j++) {
            float w = slot_w(e[j]);
            float2 f0 = __half22float2(*reinterpret_cast<const __half2*>(&pv[j].x));
            float2 f1 = __half22float2(*reinterpret_cast<const __half2*>(&pv[j].y));
            acc.x += w * f0.x;
            acc.y += w * f0.y;
            acc.z += w * f1.x;
            acc.w += w * f1.y;
        }
    }
    for (; i < lim; i++) {
        unsigned int e = __shfl_sync(0xFFFFFFFFu, my, i);
        float w = slot_w(e);
        uint2 pk = g_Ph[(size_t)(e & 0xFFFFu) * 32 + lane];
        float2 f0 = __half22float2(*reinterpret_cast<const __half2*>(&pk.x));
        float2 f1 = __half22float2(*reinterpret_cast<const __half2*>(&pk.y));
        acc.x += w * f0.x; acc.y += w * f0.y;
        acc.z += w * f1.x; acc.w += w * f1.y;
    }
    for (; i < cnt; i++) {   // rare tail: degree > 32
        unsigned int e = __ldg(sl + i);
        float w = slot_w(e);
        uint2 pk = g_Ph[(size_t)(e & 0xFFFFu) * 32 + lane];
        float2 f0 = __half22float2(*reinterpret_cast<const __half2*>(&pk.x));
        float2 f1 = __half22float2(*reinterpret_cast<const __half2*>(&pk.y));
        acc.x += w * f0.x; acc.y += w * f0.y;
        acc.z += w * f1.x; acc.w += w * f1.y;
    }

    acc.x *= 0.5f; acc.y *= 0.5f; acc.z *= 0.5f; acc.w *= 0.5f;
    reinterpret_cast<float4*>(out)[(size_t)node * 32 + lane] = acc;

    if (lane == 0) g_cursor[node] = 0;   // restore invariant for next call
}

// ===========================================================================
// Launch. Inputs: feature [N*D] f32, edge_src [E] i32, edge_dst [E] i32,
// edge_w [E] f32, weight [D*D] f32. Output: [N*D] f32.
// ===========================================================================
extern "C" void kernel_launch(void* const* d_in, const int* in_sizes, int n_in,
                              void* d_out, int out_size) {
    const float* feat = (const float*)d_in[0];
    const int*   src  = (const int*)d_in[1];
    const int*   dst  = (const int*)d_in[2];
    const float* ew   = (const float*)d_in[3];
    const float* W    = (const float*)d_in[4];
    float* out = (float*)d_out;

    const int E  = in_sizes[1];
    const int FB = (E + 255) / 256;

    gemm_fill_kernel<<<GB + FB, 256>>>(feat, W, src, dst, ew, E);
    gather_kernel<<<(N_NODES * 32 + 255) / 256, 256>>>(out);
}